// round 7
// baseline (speedup 1.0000x reference)
#include <cuda_runtime.h>
#include <cuda_bf16.h>
#include <math.h>
#include <stdint.h>

#define CC     512
#define T_LEN  2048
#define BATCH  4
#define NH     8
#define HD     64

// Scratch (allocation-free rule: __device__ globals)
#define W_ELEMS (3 * CC * CC + CC * CC)             // qkv_w then proj_w
#define X_ELEMS ((size_t)BATCH * CC * T_LEN)
#define QKV_ELEMS ((size_t)BATCH * 3 * CC * T_LEN)
__device__ __nv_bfloat16 g_whi[W_ELEMS];
__device__ __nv_bfloat16 g_wlo[W_ELEMS];
__device__ __nv_bfloat16 g_xhi[X_ELEMS];            // x split, later attn output split
__device__ __nv_bfloat16 g_xlo[X_ELEMS];
__device__ __nv_bfloat16 g_qkvhi[QKV_ELEMS];        // QKV GEMM output (hi/lo)
__device__ __nv_bfloat16 g_qkvlo[QKV_ELEMS];

// ===========================================================================
// helpers
// ===========================================================================
__device__ __forceinline__ uint32_t smem_u32(const void* p) {
    uint32_t a;
    asm("{ .reg .u64 t; cvta.to.shared.u64 t, %1; cvt.u32.u64 %0, t; }" : "=r"(a) : "l"(p));
    return a;
}
__device__ __forceinline__ uint32_t pk_bf2(__nv_bfloat16 a, __nv_bfloat16 b) {
    __nv_bfloat162 t(a, b);
    return *reinterpret_cast<uint32_t*>(&t);
}
__device__ __forceinline__ void split2(float x, float y, uint32_t& hi, uint32_t& lo) {
    __nv_bfloat16 xh = __float2bfloat16(x), yh = __float2bfloat16(y);
    __nv_bfloat16 xl = __float2bfloat16(x - __bfloat162float(xh));
    __nv_bfloat16 yl = __float2bfloat16(y - __bfloat162float(yh));
    hi = pk_bf2(xh, yh);
    lo = pk_bf2(xl, yl);
}
__device__ __forceinline__ void ldsm4(uint32_t& r0, uint32_t& r1, uint32_t& r2, uint32_t& r3,
                                      uint32_t addr) {
    asm volatile("ldmatrix.sync.aligned.m8n8.x4.shared.b16 {%0,%1,%2,%3}, [%4];"
                 : "=r"(r0), "=r"(r1), "=r"(r2), "=r"(r3) : "r"(addr));
}
__device__ __forceinline__ void ldsm4t(uint32_t& r0, uint32_t& r1, uint32_t& r2, uint32_t& r3,
                                       uint32_t addr) {
    asm volatile("ldmatrix.sync.aligned.m8n8.x4.trans.shared.b16 {%0,%1,%2,%3}, [%4];"
                 : "=r"(r0), "=r"(r1), "=r"(r2), "=r"(r3) : "r"(addr));
}
__device__ __forceinline__ void mma16816(float* c, uint32_t a0, uint32_t a1, uint32_t a2,
                                         uint32_t a3, uint32_t b0, uint32_t b1) {
    asm volatile(
        "mma.sync.aligned.m16n8k16.row.col.f32.bf16.bf16.f32 "
        "{%0,%1,%2,%3}, {%4,%5,%6,%7}, {%8,%9}, {%0,%1,%2,%3};"
        : "+f"(c[0]), "+f"(c[1]), "+f"(c[2]), "+f"(c[3])
        : "r"(a0), "r"(a1), "r"(a2), "r"(a3), "r"(b0), "r"(b1));
}
__device__ __forceinline__ void cp16(uint32_t dst, const void* src) {
    asm volatile("cp.async.cg.shared.global [%0], [%1], 16;" :: "r"(dst), "l"(src));
}
#define CP_COMMIT() asm volatile("cp.async.commit_group;" ::: "memory")
#define CP_WAIT0()  asm volatile("cp.async.wait_group 0;" ::: "memory")

// ===========================================================================
// prep: fp32 -> bf16 hi/lo split
// ===========================================================================
__global__ void __launch_bounds__(256) split_f32(
    const float* __restrict__ src, __nv_bfloat16* __restrict__ hi,
    __nv_bfloat16* __restrict__ lo, int n4)
{
    int i = blockIdx.x * blockDim.x + threadIdx.x;
    if (i >= n4) return;
    float4 v = ((const float4*)src)[i];
    uint32_t h0, l0, h1, l1;
    split2(v.x, v.y, h0, l0);
    split2(v.z, v.w, h1, l1);
    ((uint2*)hi)[i] = make_uint2(h0, h1);
    ((uint2*)lo)[i] = make_uint2(l0, l1);
}

// ===========================================================================
// bf16 3-term GEMM, tile 128x128x32, 8 warps (4M x 2N), cp.async 2-stage
// ===========================================================================
#define ASTR 80
#define BSTR 272
#define SA_HI 0
#define SA_LO 10240
#define SB_HI 20480
#define SB_LO 29184
#define GSTAGE 37888
#define GEMM_SMEM (2 * GSTAGE)

template<bool RES, bool SPLITOUT>
__global__ void __launch_bounds__(256, 2) gemm_bf16(
    const __nv_bfloat16* __restrict__ Ahi, const __nv_bfloat16* __restrict__ Alo,
    const __nv_bfloat16* __restrict__ Bhi, const __nv_bfloat16* __restrict__ Blo,
    const float* __restrict__ bias, const float* __restrict__ res,
    float* __restrict__ C, __nv_bfloat16* __restrict__ Chi, __nv_bfloat16* __restrict__ Clo,
    int M, int N, int K)
{
    extern __shared__ char sm[];
    const int z  = blockIdx.z;
    const int n0 = blockIdx.x * 128;
    const int m0 = blockIdx.y * 128;
    const int tid  = threadIdx.x;
    const int wid  = tid >> 5;
    const int lane = tid & 31;
    const int wm = wid & 3;
    const int wn = wid >> 2;

    const __nv_bfloat16* Bhz = Bhi + (size_t)z * K * N;
    const __nv_bfloat16* Blz = Blo + (size_t)z * K * N;

    float acc[2][8][4];
#pragma unroll
    for (int i = 0; i < 2; i++)
#pragma unroll
        for (int j = 0; j < 8; j++)
#pragma unroll
            for (int e = 0; e < 4; e++) acc[i][j][e] = 0.f;

    const uint32_t smb = smem_u32(sm);
    const int lr = lane & 15;
    const int lc = lane >> 4;
    const uint32_t aRel = SA_HI + (uint32_t)(wm * 32 + lr) * ASTR + lc * 16;
    const uint32_t bRel = SB_HI + (uint32_t)lr * BSTR + wn * 128 + lc * 16;

    // per-thread load coords
    const int am = tid >> 2, ak = (tid & 3) << 3;
    const int bk = tid >> 4, bn = (tid & 15) << 3;
    const int am2 = (tid + 256) >> 2, ak2 = ((tid + 256) & 3) << 3;
    const int bk2 = (tid + 256) >> 4, bn2 = ((tid + 256) & 15) << 3;

    const int KS = K >> 5;

    auto load_slab = [&](int k0, int st) {
        uint32_t base = smb + (uint32_t)st * GSTAGE;
        size_t ga  = (size_t)(m0 + am)  * K + k0 + ak;
        size_t ga2 = (size_t)(m0 + am2) * K + k0 + ak2;
        size_t gb  = (size_t)(k0 + bk)  * N + n0 + bn;
        size_t gb2 = (size_t)(k0 + bk2) * N + n0 + bn2;
        cp16(base + SA_HI + am * ASTR + ak * 2,  Ahi + ga);
        cp16(base + SA_LO + am * ASTR + ak * 2,  Alo + ga);
        cp16(base + SA_HI + am2 * ASTR + ak2 * 2, Ahi + ga2);
        cp16(base + SA_LO + am2 * ASTR + ak2 * 2, Alo + ga2);
        cp16(base + SB_HI + bk * BSTR + bn * 2,  Bhz + gb);
        cp16(base + SB_LO + bk * BSTR + bn * 2,  Blz + gb);
        cp16(base + SB_HI + bk2 * BSTR + bn2 * 2, Bhz + gb2);
        cp16(base + SB_LO + bk2 * BSTR + bn2 * 2, Blz + gb2);
    };

    load_slab(0, 0);
    CP_COMMIT();

    int stage = 0;
    for (int it = 0; it < KS; ++it) {
        CP_WAIT0();
        __syncthreads();
        if (it + 1 < KS) { load_slab((it + 1) << 5, stage ^ 1); CP_COMMIT(); }

        const uint32_t stb = (uint32_t)stage * GSTAGE;
        const uint32_t aAddr = smb + stb + aRel;
        const uint32_t bAddr = smb + stb + bRel;
#pragma unroll
        for (int ks = 0; ks < 2; ++ks) {
            uint32_t bh[4][4], bl[4][4];
#pragma unroll
            for (int g = 0; g < 4; ++g) {
                uint32_t base = bAddr + ks * (16 * BSTR) + g * 32;
                ldsm4t(bh[g][0], bh[g][1], bh[g][2], bh[g][3], base);
                ldsm4t(bl[g][0], bl[g][1], bl[g][2], bl[g][3], base + (SB_LO - SB_HI));
            }
#pragma unroll
            for (int mt = 0; mt < 2; ++mt) {
                uint32_t abase = aAddr + mt * (16 * ASTR) + ks * 32;
                uint32_t ah0, ah1, ah2, ah3, al0, al1, al2, al3;
                ldsm4(ah0, ah1, ah2, ah3, abase);
                ldsm4(al0, al1, al2, al3, abase + (SA_LO - SA_HI));
#pragma unroll
                for (int g = 0; g < 4; ++g) {
                    float* c0 = acc[mt][2 * g];
                    float* c1 = acc[mt][2 * g + 1];
                    mma16816(c0, ah0, ah1, ah2, ah3, bh[g][0], bh[g][1]);
                    mma16816(c0, ah0, ah1, ah2, ah3, bl[g][0], bl[g][1]);
                    mma16816(c0, al0, al1, al2, al3, bh[g][0], bh[g][1]);
                    mma16816(c1, ah0, ah1, ah2, ah3, bh[g][2], bh[g][3]);
                    mma16816(c1, ah0, ah1, ah2, ah3, bl[g][2], bl[g][3]);
                    mma16816(c1, al0, al1, al2, al3, bh[g][2], bh[g][3]);
                }
            }
        }
        stage ^= 1;
    }

#pragma unroll
    for (int mt = 0; mt < 2; ++mt) {
        int r1 = m0 + wm * 32 + mt * 16 + (lane >> 2);
        int r2 = r1 + 8;
        float b1 = bias[r1];
        float b2 = bias[r2];
#pragma unroll
        for (int g = 0; g < 8; ++g) {
            int col = n0 + wn * 64 + g * 8 + ((lane & 3) << 1);
            float2 w1 = make_float2(acc[mt][g][0] + b1, acc[mt][g][1] + b1);
            float2 w2 = make_float2(acc[mt][g][2] + b2, acc[mt][g][3] + b2);
            if (SPLITOUT) {
                __nv_bfloat16* ChZ = Chi + (size_t)z * M * N;
                __nv_bfloat16* ClZ = Clo + (size_t)z * M * N;
                uint32_t hh, ll;
                split2(w1.x, w1.y, hh, ll);
                *(uint32_t*)(ChZ + (size_t)r1 * N + col) = hh;
                *(uint32_t*)(ClZ + (size_t)r1 * N + col) = ll;
                split2(w2.x, w2.y, hh, ll);
                *(uint32_t*)(ChZ + (size_t)r2 * N + col) = hh;
                *(uint32_t*)(ClZ + (size_t)r2 * N + col) = ll;
            } else {
                float* Cz = C + (size_t)z * M * N;
                if (RES) {
                    float2 q1 = *(const float2*)(res + (size_t)z * M * N + (size_t)r1 * N + col);
                    float2 q2 = *(const float2*)(res + (size_t)z * M * N + (size_t)r2 * N + col);
                    w1.x += q1.x; w1.y += q1.y;
                    w2.x += q2.x; w2.y += q2.y;
                }
                *(float2*)(Cz + (size_t)r1 * N + col) = w1;
                *(float2*)(Cz + (size_t)r2 * N + col) = w2;
            }
        }
    }
}

// ===========================================================================
// Attention: mma.sync bf16 3-term, cp.async 2-stage K/V pipeline
// ===========================================================================
#define BT2 128
#define BS2 64
#define NIT (T_LEN / BS2)

#define QSTR 272
#define KSTR 144
#define SM_QHI 0
#define SM_QLO 17408
#define SM_KV  34816
#define KVS_K_HI 0
#define KVS_K_LO 9216
#define KVS_V_HI 18432
#define KVS_V_LO 27648
#define KVSTAGE 36864
#define ATTN_SMEM (SM_KV + 2 * KVSTAGE)    // 108544

__global__ void __launch_bounds__(256, 2) attn_mma()
{
    extern __shared__ char sm[];
    const int tid  = threadIdx.x;
    const int wid  = tid >> 5;
    const int lane = tid & 31;
    const int t0 = blockIdx.x * BT2;
    const int h  = blockIdx.y;
    const int b  = blockIdx.z;

    const size_t qoff = ((size_t)b * 3 * CC + h * HD) * T_LEN;
    const __nv_bfloat16* qhi = g_qkvhi + qoff;
    const __nv_bfloat16* qlo = g_qkvlo + qoff;
    const __nv_bfloat16* khi = qhi + (size_t)CC * T_LEN;
    const __nv_bfloat16* klo = qlo + (size_t)CC * T_LEN;
    const __nv_bfloat16* vhi = khi + (size_t)CC * T_LEN;
    const __nv_bfloat16* vlo = klo + (size_t)CC * T_LEN;

    const uint32_t smb = smem_u32(sm);

    // K/V tile loader: [d=64][s=64] pure cp.async copies
    const int kvd = tid >> 3, kvc = tid & 7;
    const int kvd2 = (tid + 256) >> 3, kvc2 = (tid + 256) & 7;
    auto kv_load = [&](int s0, int st) {
        uint32_t base = smb + SM_KV + (uint32_t)st * KVSTAGE;
        size_t g  = (size_t)kvd * T_LEN + s0 + kvc * 8;
        size_t g2 = (size_t)kvd2 * T_LEN + s0 + kvc2 * 8;
        uint32_t o  = base + kvd * KSTR + kvc * 16;
        uint32_t o2 = base + kvd2 * KSTR + kvc2 * 16;
        cp16(o + KVS_K_HI,  khi + g);
        cp16(o + KVS_K_LO,  klo + g);
        cp16(o + KVS_V_HI,  vhi + g);
        cp16(o + KVS_V_LO,  vlo + g);
        cp16(o2 + KVS_K_HI, khi + g2);
        cp16(o2 + KVS_K_LO, klo + g2);
        cp16(o2 + KVS_V_HI, vhi + g2);
        cp16(o2 + KVS_V_LO, vlo + g2);
    };

    kv_load(0, 0);
    CP_COMMIT();

    // ---- Q tile [d=64][t=128]: pure copies (overlaps with first K/V load) ----
#pragma unroll
    for (int l = 0; l < 4; ++l) {
        int f = tid + l * 256;
        int d = f >> 4;
        int c = f & 15;
        size_t g = (size_t)d * T_LEN + t0 + c * 8;
        *(uint4*)(sm + SM_QHI + d * QSTR + c * 16) = *(const uint4*)(qhi + g);
        *(uint4*)(sm + SM_QLO + d * QSTR + c * 16) = *(const uint4*)(qlo + g);
    }

    float oacc[32];
#pragma unroll
    for (int i = 0; i < 32; ++i) oacc[i] = 0.f;
    float m_r1 = -INFINITY, m_r2 = -INFINITY, l_r1 = 0.f, l_r2 = 0.f;

    // A-frag (Q) trans-ldsm: rows=d, cols=t
    const int q8 = lane & 7;
    const int qh2 = (lane >> 3) & 1;
    const int qd2 = lane >> 4;
    const uint32_t qa_hi = smb + SM_QHI + (uint32_t)(q8 + 8 * qd2) * QSTR + wid * 32 + qh2 * 16;
    const uint32_t qa_lo = qa_hi + (SM_QLO - SM_QHI);
    // B-frag (K) trans-ldsm: rows=d(=k), cols=s
    const int lr = lane & 15;
    const int lc = lane >> 4;
    const uint32_t kb_rel = (uint32_t)lr * KSTR + lc * 16;              // + KVS_K_HI(0)
    // B-frag (V) non-trans: rows=d(=n), cols=s(=k)
    const int v8 = lane & 7;
    const int vh2 = (lane >> 3) & 1;
    const int vd2 = lane >> 4;
    const uint32_t vb_rel = KVS_V_HI + (uint32_t)(v8 + 8 * vd2) * KSTR + vh2 * 16;

    const float scale = 0.044194173824159216f;   // 512^-0.5

    int stage = 0;
    for (int it = 0; it < NIT; ++it) {
        CP_WAIT0();
        __syncthreads();
        if (it + 1 < NIT) { kv_load((it + 1) * BS2, stage ^ 1); CP_COMMIT(); }

        const uint32_t kvb = smb + SM_KV + (uint32_t)stage * KVSTAGE;
        const uint32_t kb_hi = kvb + kb_rel;
        const uint32_t kb_lo = kb_hi + KVS_K_LO;
        const uint32_t vb_hi = kvb + vb_rel;

        // ---- S = Q K^T ----
        float sacc[32];
#pragma unroll
        for (int i = 0; i < 32; ++i) sacc[i] = 0.f;
#pragma unroll
        for (int ks = 0; ks < 4; ++ks) {
            uint32_t qh0, qh1, qh2r, qh3, ql0, ql1, ql2, ql3;
            ldsm4t(qh0, qh1, qh2r, qh3, qa_hi + ks * (16 * QSTR));
            ldsm4t(ql0, ql1, ql2, ql3, qa_lo + ks * (16 * QSTR));
#pragma unroll
            for (int np = 0; np < 4; ++np) {
                uint32_t bh0, bh1, bh2, bh3, bl0, bl1, bl2, bl3;
                ldsm4t(bh0, bh1, bh2, bh3, kb_hi + ks * (16 * KSTR) + np * 32);
                ldsm4t(bl0, bl1, bl2, bl3, kb_lo + ks * (16 * KSTR) + np * 32);
                float* c0 = &sacc[np * 8];
                float* c1 = &sacc[np * 8 + 4];
                mma16816(c0, qh0, qh1, qh2r, qh3, bh0, bh1);
                mma16816(c0, qh0, qh1, qh2r, qh3, bl0, bl1);
                mma16816(c0, ql0, ql1, ql2, ql3, bh0, bh1);
                mma16816(c1, qh0, qh1, qh2r, qh3, bh2, bh3);
                mma16816(c1, qh0, qh1, qh2r, qh3, bl2, bl3);
                mma16816(c1, ql0, ql1, ql2, ql3, bh2, bh3);
            }
        }

        // ---- scale + online softmax ----
#pragma unroll
        for (int i = 0; i < 32; ++i) sacc[i] *= scale;
        float nm1 = -INFINITY, nm2 = -INFINITY;
#pragma unroll
        for (int j = 0; j < 8; ++j) {
            nm1 = fmaxf(nm1, fmaxf(sacc[4 * j],     sacc[4 * j + 1]));
            nm2 = fmaxf(nm2, fmaxf(sacc[4 * j + 2], sacc[4 * j + 3]));
        }
        nm1 = fmaxf(nm1, __shfl_xor_sync(0xffffffffu, nm1, 1));
        nm1 = fmaxf(nm1, __shfl_xor_sync(0xffffffffu, nm1, 2));
        nm2 = fmaxf(nm2, __shfl_xor_sync(0xffffffffu, nm2, 1));
        nm2 = fmaxf(nm2, __shfl_xor_sync(0xffffffffu, nm2, 2));
        const float mn1 = fmaxf(m_r1, nm1);
        const float mn2 = fmaxf(m_r2, nm2);
        const float a1 = __expf(m_r1 - mn1);
        const float a2 = __expf(m_r2 - mn2);
        float s1 = 0.f, s2 = 0.f;
#pragma unroll
        for (int j = 0; j < 8; ++j) {
            float e0 = __expf(sacc[4 * j]     - mn1);
            float e1 = __expf(sacc[4 * j + 1] - mn1);
            float e2 = __expf(sacc[4 * j + 2] - mn2);
            float e3 = __expf(sacc[4 * j + 3] - mn2);
            sacc[4 * j] = e0; sacc[4 * j + 1] = e1; sacc[4 * j + 2] = e2; sacc[4 * j + 3] = e3;
            s1 += e0 + e1;
            s2 += e2 + e3;
        }
        s1 += __shfl_xor_sync(0xffffffffu, s1, 1);
        s1 += __shfl_xor_sync(0xffffffffu, s1, 2);
        s2 += __shfl_xor_sync(0xffffffffu, s2, 1);
        s2 += __shfl_xor_sync(0xffffffffu, s2, 2);
        l_r1 = l_r1 * a1 + s1;
        l_r2 = l_r2 * a2 + s2;
        m_r1 = mn1;
        m_r2 = mn2;
#pragma unroll
        for (int j = 0; j < 8; ++j) {
            oacc[4 * j]     *= a1;
            oacc[4 * j + 1] *= a1;
            oacc[4 * j + 2] *= a2;
            oacc[4 * j + 3] *= a2;
        }

        // ---- O += P V^T ----
#pragma unroll
        for (int ks = 0; ks < 4; ++ks) {
            const float* sA = &sacc[8 * ks];
            uint32_t ph0, ph1, ph2, ph3, pl0, pl1, pl2, pl3;
            split2(sA[0], sA[1], ph0, pl0);
            split2(sA[2], sA[3], ph1, pl1);
            split2(sA[4], sA[5], ph2, pl2);
            split2(sA[6], sA[7], ph3, pl3);
#pragma unroll
            for (int np = 0; np < 4; ++np) {
                uint32_t bh0, bh1, bh2, bh3, bl0, bl1, bl2, bl3;
                uint32_t base = vb_hi + np * (16 * KSTR) + ks * 32;
                ldsm4(bh0, bh1, bh2, bh3, base);
                ldsm4(bl0, bl1, bl2, bl3, base + (KVS_V_LO - KVS_V_HI));
                float* c0 = &oacc[np * 8];
                float* c1 = &oacc[np * 8 + 4];
                mma16816(c0, ph0, ph1, ph2, ph3, bh0, bh1);
                mma16816(c0, ph0, ph1, ph2, ph3, bl0, bl1);
                mma16816(c0, pl0, pl1, pl2, pl3, bh0, bh1);
                mma16816(c1, ph0, ph1, ph2, ph3, bh2, bh3);
                mma16816(c1, ph0, ph1, ph2, ph3, bl2, bl3);
                mma16816(c1, pl0, pl1, pl2, pl3, bh2, bh3);
            }
        }
        stage ^= 1;
    }

    __syncthreads();
    // ---- epilogue: normalize, stage [d][t] fp32, write bf16 hi/lo split ----
    {
        float* so = (float*)(sm + SM_KV);
        const float i1 = 1.f / l_r1;
        const float i2 = 1.f / l_r2;
        const int r  = lane >> 2;
        const int tw = wid * 16;
#pragma unroll
        for (int j = 0; j < 8; ++j) {
            int d0 = 8 * j + ((lane & 3) << 1);
            so[(size_t)d0 * 128 + tw + r]           = oacc[4 * j]     * i1;
            so[(size_t)(d0 + 1) * 128 + tw + r]     = oacc[4 * j + 1] * i1;
            so[(size_t)d0 * 128 + tw + r + 8]       = oacc[4 * j + 2] * i2;
            so[(size_t)(d0 + 1) * 128 + tw + r + 8] = oacc[4 * j + 3] * i2;
        }
        __syncthreads();
        const size_t obase = ((size_t)b * CC + h * HD) * T_LEN;
#pragma unroll
        for (int l = 0; l < 8; ++l) {
            int f  = tid + l * 256;
            int c  = f >> 5;
            int t4 = (f & 31) << 2;
            float4 v = *(float4*)&so[(size_t)c * 128 + t4];
            uint32_t h0, l0, h1, l1;
            split2(v.x, v.y, h0, l0);
            split2(v.z, v.w, h1, l1);
            size_t g = obase + (size_t)c * T_LEN + t0 + t4;
            *(uint2*)(g_xhi + g) = make_uint2(h0, h1);
            *(uint2*)(g_xlo + g) = make_uint2(l0, l1);
        }
    }
}

// ===========================================================================
extern "C" void kernel_launch(void* const* d_in, const int* in_sizes, int n_in,
                              void* d_out, int out_size)
{
    const float* x      = (const float*)d_in[0];
    const float* qkv_w  = (const float*)d_in[1];
    const float* qkv_b  = (const float*)d_in[2];
    const float* proj_w = (const float*)d_in[3];
    const float* proj_b = (const float*)d_in[4];
    float* out = (float*)d_out;

    __nv_bfloat16 *whi, *wlo, *xhi, *xlo, *qkvhi, *qkvlo;
    cudaGetSymbolAddress((void**)&whi, g_whi);
    cudaGetSymbolAddress((void**)&wlo, g_wlo);
    cudaGetSymbolAddress((void**)&xhi, g_xhi);
    cudaGetSymbolAddress((void**)&xlo, g_xlo);
    cudaGetSymbolAddress((void**)&qkvhi, g_qkvhi);
    cudaGetSymbolAddress((void**)&qkvlo, g_qkvlo);

    cudaFuncSetAttribute((const void*)attn_mma,
                         cudaFuncAttributeMaxDynamicSharedMemorySize, ATTN_SMEM);
    cudaFuncSetAttribute((const void*)gemm_bf16<false, true>,
                         cudaFuncAttributeMaxDynamicSharedMemorySize, GEMM_SMEM);
    cudaFuncSetAttribute((const void*)gemm_bf16<true, false>,
                         cudaFuncAttributeMaxDynamicSharedMemorySize, GEMM_SMEM);

    const int QW4 = (3 * CC * CC) / 4;
    const int PW4 = (CC * CC) / 4;
    const int X4  = (int)(X_ELEMS / 4);
    const int PW_OFF = 3 * CC * CC;

    split_f32<<<(QW4 + 255) / 256, 256>>>(qkv_w, whi, wlo, QW4);
    split_f32<<<(PW4 + 255) / 256, 256>>>(proj_w, whi + PW_OFF, wlo + PW_OFF, PW4);
    split_f32<<<(X4 + 255) / 256, 256>>>(x, xhi, xlo, X4);

    // 1) qkv = W_qkv @ x + b  -> bf16 hi/lo
    gemm_bf16<false, true><<<dim3(T_LEN / 128, (3 * CC) / 128, BATCH), 256, GEMM_SMEM>>>(
        whi, wlo, xhi, xlo, qkv_b, nullptr, nullptr, qkvhi, qkvlo, 3 * CC, T_LEN, CC);

    // 2) attention (writes bf16 hi/lo into xhi/xlo)
    attn_mma<<<dim3(T_LEN / BT2, NH, BATCH), 256, ATTN_SMEM>>>();

    // 3) out = x + W_proj @ att + b  (fp32 out)
    gemm_bf16<true, false><<<dim3(T_LEN / 128, CC / 128, BATCH), 256, GEMM_SMEM>>>(
        whi + PW_OFF, wlo + PW_OFF, xhi, xlo, proj_b, x, out, nullptr, nullptr, CC, T_LEN, CC);
}